// round 5
// baseline (speedup 1.0000x reference)
#include <cuda_runtime.h>
#include <cuda_fp16.h>
#include <cstdint>

// ============================================================================
// LSTMCell on sm_100 (baseline PTX: no tcgen05). mma.sync.m16n8k16 f16/f32.
// a = b + x@W + h@V ; i,f,o = sigmoid ; g = tanh ; c' = i*g + f*c ; h' = o*tanh(c')
// x,h:(4096,1024) c:(4096,1024) W,V:(1024,4096) b:(4096)
// out = [h_out (4096x1024) | c_out (4096x1024)]
//
// pack_A: [x|h] -> fp16 row-major [4096][2048]
// pack_B: [W;V] -> fp16 transposed+permuted [N'=4096][K=2048], where
//         n' = 128*(j/32) + 32*((j/8)&3) + 8*g + (j&7)  (j = n%1024, g = n/1024)
//         so each warp's four n8 MMA tiles are the four gates at identical j cols.
// lstm_main: 128x128 CTA tile, BK=32, 4-stage cp.async pipeline, 8 warps (2x4),
//         warp tile 64x32 (4 m16 x 4 n8=gates). Epilogue fully in-register.
// ============================================================================

#define BATCH 4096
#define KTOT  2048
#define BM 128
#define BN 128
#define BK 32
#define STAGES 4
#define STAGE_BYTES 16384  // A: 128x32 fp16 (8KB) + B: 128x32 fp16 (8KB)

__device__ __align__(16) __half g_Apack[(size_t)BATCH * KTOT];  // 16 MB
__device__ __align__(16) __half g_Bpack[(size_t)4096 * KTOT];   // 16 MB

// ---------------------------------------------------------------- helpers
__device__ __forceinline__ uint32_t smem_u32(const void* p) {
    uint32_t a;
    asm("{ .reg .u64 t; cvta.to.shared.u64 t, %1; cvt.u32.u64 %0, t; }" : "=r"(a) : "l"(p));
    return a;
}
__device__ __forceinline__ void cpasync16(uint32_t dst, const void* src) {
    asm volatile("cp.async.cg.shared.global [%0], [%1], 16;" :: "r"(dst), "l"(src));
}
__device__ __forceinline__ void cp_commit() { asm volatile("cp.async.commit_group;" ::: "memory"); }
template <int N>
__device__ __forceinline__ void cp_wait() { asm volatile("cp.async.wait_group %0;" :: "n"(N) : "memory"); }

// smem layout: 64B rows (32 halfs). chunk c16 in 0..3 permuted so the 8 rows of
// any ldmatrix phase hit the 8 distinct 16B slots mod 128B (conflict-free).
__device__ __forceinline__ uint32_t swz(uint32_t r, uint32_t c16) {
    return r * 64u + (((c16 ^ (r & 3u) ^ ((r >> 2) & 1u)) & 3u) << 4);
}

__device__ __forceinline__ void ldsm_x4(uint32_t* r, uint32_t addr) {
    asm volatile("ldmatrix.sync.aligned.m8n8.x4.shared.b16 {%0,%1,%2,%3}, [%4];"
                 : "=r"(r[0]), "=r"(r[1]), "=r"(r[2]), "=r"(r[3]) : "r"(addr));
}
__device__ __forceinline__ void mma16816(float* c, const uint32_t* a, const uint32_t* b) {
    asm volatile(
        "mma.sync.aligned.m16n8k16.row.col.f32.f16.f16.f32 "
        "{%0,%1,%2,%3}, {%4,%5,%6,%7}, {%8,%9}, {%0,%1,%2,%3};"
        : "+f"(c[0]), "+f"(c[1]), "+f"(c[2]), "+f"(c[3])
        : "r"(a[0]), "r"(a[1]), "r"(a[2]), "r"(a[3]), "r"(b[0]), "r"(b[1]));
}

__device__ __forceinline__ float sigm_f(float x) { return __fdividef(1.0f, 1.0f + __expf(-x)); }
__device__ __forceinline__ float tanh_f(float x) { return __fdividef(2.0f, 1.0f + __expf(-2.0f * x)) - 1.0f; }

// ---------------------------------------------------------------- pack A
__global__ void __launch_bounds__(256) pack_A(const float* __restrict__ x,
                                              const float* __restrict__ h) {
    size_t t = (size_t)blockIdx.x * 256 + threadIdx.x;   // one float4 per thread
    size_t base = t * 4;
    int m = (int)(base >> 11);
    int k = (int)(base & 2047);
    const float* src = (k < 1024) ? (x + (size_t)m * 1024 + k)
                                  : (h + (size_t)m * 1024 + (k - 1024));
    float4 v = *reinterpret_cast<const float4*>(src);
    __half2 lo = __floats2half2_rn(v.x, v.y);
    __half2 hi = __floats2half2_rn(v.z, v.w);
    uint2 pk = make_uint2(*reinterpret_cast<uint32_t*>(&lo), *reinterpret_cast<uint32_t*>(&hi));
    *reinterpret_cast<uint2*>(&g_Apack[base]) = pk;
}

// ---------------------------------------------------------------- pack B
__global__ void __launch_bounds__(256) pack_B(const float* __restrict__ W,
                                              const float* __restrict__ V) {
    __shared__ float buf[32][33];
    const int nblk = blockIdx.x;   // 0..127 (orig n / 32)
    const int kblk = blockIdx.y;   // 0..63  (k / 32)
    const int n0 = nblk * 32, k0 = kblk * 32;
    const float* src = (k0 < 1024) ? (W + (size_t)k0 * 4096 + n0)
                                   : (V + (size_t)(k0 - 1024) * 4096 + n0);
    for (int idx = threadIdx.x; idx < 1024; idx += 256) {
        int kl = idx >> 5, nl = idx & 31;
        buf[kl][nl] = src[(size_t)kl * 4096 + nl];
    }
    __syncthreads();
    for (int idx = threadIdx.x; idx < 512; idx += 256) {
        int nl = idx >> 4;            // 0..31
        int kp = (idx & 15) * 2;      // 0..30 step 2
        int norig = n0 + nl;
        int g = norig >> 10;
        int rem = norig & 1023;
        int np = ((rem >> 5) << 7) + (((rem >> 3) & 3) << 5) + (g << 3) + (rem & 7);
        __half2 hv = __floats2half2_rn(buf[kp][nl], buf[kp + 1][nl]);
        *reinterpret_cast<uint32_t*>(&g_Bpack[(size_t)np * KTOT + k0 + kp]) =
            *reinterpret_cast<uint32_t*>(&hv);
    }
}

// ---------------------------------------------------------------- main GEMM + epilogue
__global__ void __launch_bounds__(256, 2) lstm_main(const float* __restrict__ c_in,
                                                    const float* __restrict__ bias,
                                                    float* __restrict__ out) {
    extern __shared__ __align__(128) unsigned char smem[];
    const uint32_t sb = smem_u32(smem);
    const int tid  = threadIdx.x;
    const int lane = tid & 31;
    const int warp = tid >> 5;
    const int wm = warp >> 2;       // 0..1  (64 rows each)
    const int wn = warp & 3;        // 0..3  (32 B'-cols = 4 gates x 8 j)
    const int bx = blockIdx.x;      // j-block (32 cols)
    const int by = blockIdx.y;      // m-block (128 rows)

    const __half* Ap = g_Apack + (size_t)by * BM * KTOT;
    const __half* Bp = g_Bpack + (size_t)bx * BN * KTOT;

    auto load_stage = [&](int it) {
        const uint32_t st = sb + (uint32_t)(it & (STAGES - 1)) * STAGE_BYTES;
        const int k0 = it * BK;
#pragma unroll
        for (int i = 0; i < 2; i++) {
            int idx = tid + i * 256;          // 0..511
            uint32_t r = (uint32_t)(idx >> 2);
            uint32_t c16 = (uint32_t)(idx & 3);
            cpasync16(st + swz(r, c16), Ap + (size_t)r * KTOT + k0 + c16 * 8);
            cpasync16(st + 8192 + swz(r, c16), Bp + (size_t)r * KTOT + k0 + c16 * 8);
        }
        cp_commit();
    };

    float acc[4][4][4];
#pragma unroll
    for (int i = 0; i < 4; i++)
#pragma unroll
        for (int j = 0; j < 4; j++)
#pragma unroll
            for (int q = 0; q < 4; q++) acc[i][j][q] = 0.0f;

    load_stage(0); load_stage(1); load_stage(2);

    const int NIT = KTOT / BK;  // 64
    for (int it = 0; it < NIT; ++it) {
        cp_wait<STAGES - 2>();
        __syncthreads();
        const uint32_t sA = sb + (uint32_t)(it & (STAGES - 1)) * STAGE_BYTES;
        const uint32_t sB = sA + 8192;
        const uint32_t rlo = (uint32_t)(lane & 15);
        const uint32_t csel = (uint32_t)(lane >> 4);
#pragma unroll
        for (int k16 = 0; k16 < 2; ++k16) {
            uint32_t a[4][4];
#pragma unroll
            for (int mt = 0; mt < 4; ++mt) {
                uint32_t row = (uint32_t)(wm * 64 + mt * 16) + rlo;
                ldsm_x4(a[mt], sA + swz(row, 2 * k16 + csel));
            }
            uint32_t b[4][2];
#pragma unroll
            for (int gp = 0; gp < 2; ++gp) {
                uint32_t r4[4];
                uint32_t row = (uint32_t)(wn * 32 + gp * 16) + rlo;
                ldsm_x4(r4, sB + swz(row, 2 * k16 + csel));
                b[2 * gp + 0][0] = r4[0]; b[2 * gp + 1][0] = r4[1];
                b[2 * gp + 0][1] = r4[2]; b[2 * gp + 1][1] = r4[3];
            }
#pragma unroll
            for (int mt = 0; mt < 4; ++mt)
#pragma unroll
                for (int nt = 0; nt < 4; ++nt)
                    mma16816(acc[mt][nt], a[mt], b[nt]);
        }
        __syncthreads();
        if (it + 3 < NIT) load_stage(it + 3);
    }

    // ---- epilogue (fully in-register: nt == gate)
    const int jg = bx * 32 + wn * 8 + 2 * (lane & 3);
    float bi[4][2];
#pragma unroll
    for (int g = 0; g < 4; ++g) {
        bi[g][0] = bias[g * 1024 + jg];
        bi[g][1] = bias[g * 1024 + jg + 1];
    }
#pragma unroll
    for (int mt = 0; mt < 4; ++mt) {
#pragma unroll
        for (int hr = 0; hr < 2; ++hr) {
            int m = by * 128 + wm * 64 + mt * 16 + (lane >> 2) + hr * 8;
            const float2 cv = *reinterpret_cast<const float2*>(c_in + (size_t)m * 1024 + jg);
            float hv[2], co[2];
#pragma unroll
            for (int q = 0; q < 2; ++q) {
                float ai = acc[mt][0][hr * 2 + q] + bi[0][q];
                float af = acc[mt][1][hr * 2 + q] + bi[1][q];
                float ao = acc[mt][2][hr * 2 + q] + bi[2][q];
                float ag = acc[mt][3][hr * 2 + q] + bi[3][q];
                float iv = sigm_f(ai);
                float fv = sigm_f(af);
                float ov = sigm_f(ao);
                float gv = tanh_f(ag);
                float cc = (q == 0) ? cv.x : cv.y;
                float c2 = fmaf(iv, gv, fv * cc);
                co[q] = c2;
                hv[q] = ov * tanh_f(c2);
            }
            *reinterpret_cast<float2*>(out + (size_t)m * 1024 + jg) = make_float2(hv[0], hv[1]);
            *reinterpret_cast<float2*>(out + (size_t)BATCH * 1024 + (size_t)m * 1024 + jg) =
                make_float2(co[0], co[1]);
        }
    }
}

// ---------------------------------------------------------------- launch
extern "C" void kernel_launch(void* const* d_in, const int* in_sizes, int n_in,
                              void* d_out, int out_size) {
    (void)in_sizes; (void)n_in; (void)out_size;
    const float* x = (const float*)d_in[0];
    const float* h = (const float*)d_in[1];
    const float* c = (const float*)d_in[2];
    const float* W = (const float*)d_in[3];
    const float* V = (const float*)d_in[4];
    const float* b = (const float*)d_in[5];
    float* out = (float*)d_out;

    cudaFuncSetAttribute(lstm_main, cudaFuncAttributeMaxDynamicSharedMemorySize,
                         STAGES * STAGE_BYTES);

    pack_A<<<(BATCH * KTOT / 4) / 256, 256>>>(x, h);
    pack_B<<<dim3(128, 64), 256>>>(W, V);
    lstm_main<<<dim3(32, 32), 256, STAGES * STAGE_BYTES>>>(c, b, out);
}

// round 6
// speedup vs baseline: 1.0751x; 1.0751x over previous
#include <cuda_runtime.h>
#include <cuda_fp16.h>
#include <cstdint>

// ============================================================================
// LSTMCell on sm_100 (baseline PTX). mma.sync.m16n8k16 f16/f32.
// a = b + x@W + h@V ; i,f,o = sigmoid ; g = tanh ; c' = i*g + f*c ; h' = o*tanh(c')
// out = [h_out (4096x1024) | c_out (4096x1024)]
//
// R5 -> R6: smem-port-bound fix. Warp tile 64x32 -> 64x64 (4 warps per
// 128x128 CTA), BK 32 -> 64, 3-stage pipeline with ONE syncthreads/iter.
// Fragment traffic per flop drops 1.5x, barriers 4x.
// ============================================================================

#define BATCH 4096
#define KTOT  2048
#define BM 128
#define BN 128
#define BK 64
#define STAGES 3
#define A_STAGE_BYTES 16384               // 128 rows x 64 halfs (128B rows)
#define B_STAGE_BYTES 16384
#define STAGE_BYTES   32768

__device__ __align__(16) __half g_Apack[(size_t)BATCH * KTOT];  // 16 MB
__device__ __align__(16) __half g_Bpack[(size_t)4096 * KTOT];   // 16 MB

// ---------------------------------------------------------------- helpers
__device__ __forceinline__ uint32_t smem_u32(const void* p) {
    uint32_t a;
    asm("{ .reg .u64 t; cvta.to.shared.u64 t, %1; cvt.u32.u64 %0, t; }" : "=r"(a) : "l"(p));
    return a;
}
__device__ __forceinline__ void cpasync16(uint32_t dst, const void* src) {
    asm volatile("cp.async.cg.shared.global [%0], [%1], 16;" :: "r"(dst), "l"(src));
}
__device__ __forceinline__ void cp_commit() { asm volatile("cp.async.commit_group;" ::: "memory"); }
template <int N>
__device__ __forceinline__ void cp_wait() { asm volatile("cp.async.wait_group %0;" :: "n"(N) : "memory"); }

// smem rows of 128B (64 halfs); 16B chunk c16 in 0..7 XOR-swizzled by row -> any
// ldmatrix phase (8 rows, fixed c16) hits 8 distinct 16B slots mod 128B.
__device__ __forceinline__ uint32_t swz(uint32_t r, uint32_t c16) {
    return r * 128u + (((c16 ^ (r & 7u)) & 7u) << 4);
}

__device__ __forceinline__ void ldsm_x4(uint32_t* r, uint32_t addr) {
    asm volatile("ldmatrix.sync.aligned.m8n8.x4.shared.b16 {%0,%1,%2,%3}, [%4];"
                 : "=r"(r[0]), "=r"(r[1]), "=r"(r[2]), "=r"(r[3]) : "r"(addr));
}
__device__ __forceinline__ void mma16816(float* c, const uint32_t* a, uint32_t b0, uint32_t b1) {
    asm volatile(
        "mma.sync.aligned.m16n8k16.row.col.f32.f16.f16.f32 "
        "{%0,%1,%2,%3}, {%4,%5,%6,%7}, {%8,%9}, {%0,%1,%2,%3};"
        : "+f"(c[0]), "+f"(c[1]), "+f"(c[2]), "+f"(c[3])
        : "r"(a[0]), "r"(a[1]), "r"(a[2]), "r"(a[3]), "r"(b0), "r"(b1));
}

__device__ __forceinline__ float sigm_f(float x) { return __fdividef(1.0f, 1.0f + __expf(-x)); }
__device__ __forceinline__ float tanh_f(float x) { return __fdividef(2.0f, 1.0f + __expf(-2.0f * x)) - 1.0f; }

// ---------------------------------------------------------------- pack A
__global__ void __launch_bounds__(256) pack_A(const float* __restrict__ x,
                                              const float* __restrict__ h) {
    size_t t = (size_t)blockIdx.x * 256 + threadIdx.x;
    size_t base = t * 4;
    int m = (int)(base >> 11);
    int k = (int)(base & 2047);
    const float* src = (k < 1024) ? (x + (size_t)m * 1024 + k)
                                  : (h + (size_t)m * 1024 + (k - 1024));
    float4 v = *reinterpret_cast<const float4*>(src);
    __half2 lo = __floats2half2_rn(v.x, v.y);
    __half2 hi = __floats2half2_rn(v.z, v.w);
    uint2 pk = make_uint2(*reinterpret_cast<uint32_t*>(&lo), *reinterpret_cast<uint32_t*>(&hi));
    *reinterpret_cast<uint2*>(&g_Apack[base]) = pk;
}

// ---------------------------------------------------------------- pack B
// g_Bpack[n'][k], n' = 128*(j/32) + 32*((j/8)&3) + 8*g + (j&7), j=n%1024, g=n/1024
__global__ void __launch_bounds__(256) pack_B(const float* __restrict__ W,
                                              const float* __restrict__ V) {
    __shared__ float buf[32][33];
    const int nblk = blockIdx.x;   // orig n / 32
    const int kblk = blockIdx.y;   // k / 32
    const int n0 = nblk * 32, k0 = kblk * 32;
    const float* src = (k0 < 1024) ? (W + (size_t)k0 * 4096 + n0)
                                   : (V + (size_t)(k0 - 1024) * 4096 + n0);
    for (int idx = threadIdx.x; idx < 1024; idx += 256) {
        int kl = idx >> 5, nl = idx & 31;
        buf[kl][nl] = src[(size_t)kl * 4096 + nl];
    }
    __syncthreads();
    for (int idx = threadIdx.x; idx < 512; idx += 256) {
        int nl = idx >> 4;
        int kp = (idx & 15) * 2;
        int norig = n0 + nl;
        int g = norig >> 10;
        int rem = norig & 1023;
        int np = ((rem >> 5) << 7) + (((rem >> 3) & 3) << 5) + (g << 3) + (rem & 7);
        __half2 hv = __floats2half2_rn(buf[kp][nl], buf[kp + 1][nl]);
        *reinterpret_cast<uint32_t*>(&g_Bpack[(size_t)np * KTOT + k0 + kp]) =
            *reinterpret_cast<uint32_t*>(&hv);
    }
}

// ---------------------------------------------------------------- main GEMM + epilogue
// grid (32 j-blocks, 32 m-blocks), 128 threads = 4 warps (wm 0..1 x wn 0..1),
// warp tile 64 rows x 64 B'cols (4 m16 x 8 n8; nt = 4*jpair + gate).
__global__ void __launch_bounds__(128, 2) lstm_main(const float* __restrict__ c_in,
                                                    const float* __restrict__ bias,
                                                    float* __restrict__ out) {
    extern __shared__ __align__(128) unsigned char smem[];
    const uint32_t sb = smem_u32(smem);
    const int tid  = threadIdx.x;
    const int lane = tid & 31;
    const int warp = tid >> 5;
    const int wm = warp >> 1;       // 0..1 (64 rows)
    const int wn = warp & 1;        // 0..1 (64 B'cols)
    const int bx = blockIdx.x;      // j-block (32 cols)
    const int by = blockIdx.y;      // m-block (128 rows)

    const __half* Ap = g_Apack + (size_t)by * BM * KTOT;
    const __half* Bp = g_Bpack + (size_t)bx * BN * KTOT;

    // 16B chunks per stage: A 128x8=1024, B 1024 -> 16 per thread
    auto load_stage = [&](int it) {
        const uint32_t st = sb + (uint32_t)(it % STAGES) * STAGE_BYTES;
        const int k0 = it * BK;
#pragma unroll
        for (int i = 0; i < 8; i++) {
            int idx = tid + i * 128;          // 0..1023
            uint32_t r = (uint32_t)(idx >> 3);
            uint32_t c16 = (uint32_t)(idx & 7);
            cpasync16(st + swz(r, c16), Ap + (size_t)r * KTOT + k0 + c16 * 8);
            cpasync16(st + A_STAGE_BYTES + swz(r, c16), Bp + (size_t)r * KTOT + k0 + c16 * 8);
        }
        cp_commit();
    };

    float acc[4][8][4];
#pragma unroll
    for (int i = 0; i < 4; i++)
#pragma unroll
        for (int j = 0; j < 8; j++)
#pragma unroll
            for (int q = 0; q < 4; q++) acc[i][j][q] = 0.0f;

    load_stage(0); load_stage(1);

    const int NIT = KTOT / BK;  // 32
    const uint32_t rlo = (uint32_t)(lane & 15);
    const uint32_t csel = (uint32_t)(lane >> 4);

    for (int it = 0; it < NIT; ++it) {
        if (it < NIT - 1) { cp_wait<1>(); } else { cp_wait<0>(); }
        __syncthreads();
        if (it + 2 < NIT) load_stage(it + 2);   // overwrites stage it-1 (all past sync)

        const uint32_t sA = sb + (uint32_t)(it % STAGES) * STAGE_BYTES;
        const uint32_t sB = sA + A_STAGE_BYTES;
#pragma unroll
        for (int k16 = 0; k16 < 4; ++k16) {
            uint32_t a[4][4];
#pragma unroll
            for (int mt = 0; mt < 4; ++mt) {
                uint32_t row = (uint32_t)(wm * 64 + mt * 16) + rlo;
                ldsm_x4(a[mt], sA + swz(row, 2 * k16 + csel));
            }
#pragma unroll
            for (int gp = 0; gp < 4; ++gp) {
                uint32_t r4[4];
                uint32_t row = (uint32_t)(wn * 64 + gp * 16) + rlo;
                ldsm_x4(r4, sB + swz(row, 2 * k16 + csel));
#pragma unroll
                for (int mt = 0; mt < 4; ++mt) {
                    mma16816(acc[mt][2 * gp + 0], a[mt], r4[0], r4[2]);
                    mma16816(acc[mt][2 * gp + 1], a[mt], r4[1], r4[3]);
                }
            }
        }
    }

    // ---- epilogue (in-register: nt = 4*jpair + gate ... nt=2*gp+h, gate=nt&3, jp=nt>>2)
#pragma unroll
    for (int jp = 0; jp < 2; ++jp) {
        const int jg = bx * 32 + (wn * 2 + jp) * 8 + 2 * (lane & 3);
        float bi[4][2];
#pragma unroll
        for (int g = 0; g < 4; ++g) {
            bi[g][0] = bias[g * 1024 + jg];
            bi[g][1] = bias[g * 1024 + jg + 1];
        }
#pragma unroll
        for (int mt = 0; mt < 4; ++mt) {
#pragma unroll
            for (int hr = 0; hr < 2; ++hr) {
                int m = by * 128 + wm * 64 + mt * 16 + (lane >> 2) + hr * 8;
                const float2 cv = *reinterpret_cast<const float2*>(c_in + (size_t)m * 1024 + jg);
                float hv[2], co[2];
#pragma unroll
                for (int q = 0; q < 2; ++q) {
                    float ai = acc[mt][jp * 4 + 0][hr * 2 + q] + bi[0][q];
                    float af = acc[mt][jp * 4 + 1][hr * 2 + q] + bi[1][q];
                    float ao = acc[mt][jp * 4 + 2][hr * 2 + q] + bi[2][q];
                    float ag = acc[mt][jp * 4 + 3][hr * 2 + q] + bi[3][q];
                    float iv = sigm_f(ai);
                    float fv = sigm_f(af);
                    float ov = sigm_f(ao);
                    float gv = tanh_f(ag);
                    float cc = (q == 0) ? cv.x : cv.y;
                    float c2 = fmaf(iv, gv, fv * cc);
                    co[q] = c2;
                    hv[q] = ov * tanh_f(c2);
                }
                *reinterpret_cast<float2*>(out + (size_t)m * 1024 + jg) = make_float2(hv[0], hv[1]);
                *reinterpret_cast<float2*>(out + (size_t)BATCH * 1024 + (size_t)m * 1024 + jg) =
                    make_float2(co[0], co[1]);
            }
        }
    }
}

// ---------------------------------------------------------------- launch
extern "C" void kernel_launch(void* const* d_in, const int* in_sizes, int n_in,
                              void* d_out, int out_size) {
    (void)in_sizes; (void)n_in; (void)out_size;
    const float* x = (const float*)d_in[0];
    const float* h = (const float*)d_in[1];
    const float* c = (const float*)d_in[2];
    const float* W = (const float*)d_in[3];
    const float* V = (const float*)d_in[4];
    const float* b = (const float*)d_in[5];
    float* out = (float*)d_out;

    cudaFuncSetAttribute(lstm_main, cudaFuncAttributeMaxDynamicSharedMemorySize,
                         STAGES * STAGE_BYTES);

    pack_A<<<(BATCH * KTOT / 4) / 256, 256>>>(x, h);
    pack_B<<<dim3(128, 64), 256>>>(W, V);
    lstm_main<<<dim3(32, 32), 128, STAGES * STAGE_BYTES>>>(c, b, out);
}

// round 7
// speedup vs baseline: 1.1115x; 1.0339x over previous
#include <cuda_runtime.h>
#include <cuda_fp16.h>
#include <cstdint>

// ============================================================================
// LSTMCell on sm_100 (baseline PTX). mma.sync.m16n8k16 f16/f32.
// R6 -> R7: occupancy/overlap fix. 2-stage pipeline (64KB smem/CTA) so 3 CTAs
// fit per SM (12 warps/SM vs 8). Packs merged into one kernel (ncu launch
// alignment: period 2 puts lstm_main at profiled slot 5, + one less launch).
// ============================================================================

#define BATCH 4096
#define KTOT  2048
#define BM 128
#define BN 128
#define BK 64
#define STAGES 2
#define A_STAGE_BYTES 16384               // 128 rows x 64 halfs (128B rows)
#define STAGE_BYTES   32768

__device__ __align__(16) __half g_Apack[(size_t)BATCH * KTOT];  // 16 MB
__device__ __align__(16) __half g_Bpack[(size_t)4096 * KTOT];   // 16 MB

// ---------------------------------------------------------------- helpers
__device__ __forceinline__ uint32_t smem_u32(const void* p) {
    uint32_t a;
    asm("{ .reg .u64 t; cvta.to.shared.u64 t, %1; cvt.u32.u64 %0, t; }" : "=r"(a) : "l"(p));
    return a;
}
__device__ __forceinline__ void cpasync16(uint32_t dst, const void* src) {
    asm volatile("cp.async.cg.shared.global [%0], [%1], 16;" :: "r"(dst), "l"(src));
}
__device__ __forceinline__ void cp_commit() { asm volatile("cp.async.commit_group;" ::: "memory"); }
template <int N>
__device__ __forceinline__ void cp_wait() { asm volatile("cp.async.wait_group %0;" :: "n"(N) : "memory"); }

// smem rows of 128B (64 halfs); 16B chunk c16 in 0..7 XOR-swizzled by row -> any
// ldmatrix phase (8 rows, fixed c16) hits 8 distinct 16B slots mod 128B.
__device__ __forceinline__ uint32_t swz(uint32_t r, uint32_t c16) {
    return r * 128u + (((c16 ^ (r & 7u)) & 7u) << 4);
}

__device__ __forceinline__ void ldsm_x4(uint32_t* r, uint32_t addr) {
    asm volatile("ldmatrix.sync.aligned.m8n8.x4.shared.b16 {%0,%1,%2,%3}, [%4];"
                 : "=r"(r[0]), "=r"(r[1]), "=r"(r[2]), "=r"(r[3]) : "r"(addr));
}
__device__ __forceinline__ void mma16816(float* c, const uint32_t* a, uint32_t b0, uint32_t b1) {
    asm volatile(
        "mma.sync.aligned.m16n8k16.row.col.f32.f16.f16.f32 "
        "{%0,%1,%2,%3}, {%4,%5,%6,%7}, {%8,%9}, {%0,%1,%2,%3};"
        : "+f"(c[0]), "+f"(c[1]), "+f"(c[2]), "+f"(c[3])
        : "r"(a[0]), "r"(a[1]), "r"(a[2]), "r"(a[3]), "r"(b0), "r"(b1));
}

__device__ __forceinline__ float sigm_f(float x) { return __fdividef(1.0f, 1.0f + __expf(-x)); }
__device__ __forceinline__ float tanh_f(float x) { return __fdividef(2.0f, 1.0f + __expf(-2.0f * x)) - 1.0f; }

// ---------------------------------------------------------------- merged pack
// blocks [0, 8192): pack_A  — g_Apack[m][k] = fp16(k<1024 ? x[m][k] : h[m][k-1024])
// blocks [8192, 16384): pack_B — g_Bpack[n'][k], n' = 128*(j/32)+32*((j/8)&3)+8*g+(j&7)
__global__ void __launch_bounds__(256) pack_all(const float* __restrict__ x,
                                                const float* __restrict__ h,
                                                const float* __restrict__ W,
                                                const float* __restrict__ V) {
    if (blockIdx.x < 8192) {
        size_t t = (size_t)blockIdx.x * 256 + threadIdx.x;
        size_t base = t * 4;
        int m = (int)(base >> 11);
        int k = (int)(base & 2047);
        const float* src = (k < 1024) ? (x + (size_t)m * 1024 + k)
                                      : (h + (size_t)m * 1024 + (k - 1024));
        float4 v = *reinterpret_cast<const float4*>(src);
        __half2 lo = __floats2half2_rn(v.x, v.y);
        __half2 hi = __floats2half2_rn(v.z, v.w);
        uint2 pk = make_uint2(*reinterpret_cast<uint32_t*>(&lo), *reinterpret_cast<uint32_t*>(&hi));
        *reinterpret_cast<uint2*>(&g_Apack[base]) = pk;
    } else {
        __shared__ float buf[32][33];
        const int idx0 = (int)blockIdx.x - 8192;
        const int nblk = idx0 & 127;   // orig n / 32
        const int kblk = idx0 >> 7;    // k / 32
        const int n0 = nblk * 32, k0 = kblk * 32;
        const float* src = (k0 < 1024) ? (W + (size_t)k0 * 4096 + n0)
                                       : (V + (size_t)(k0 - 1024) * 4096 + n0);
        for (int idx = threadIdx.x; idx < 1024; idx += 256) {
            int kl = idx >> 5, nl = idx & 31;
            buf[kl][nl] = src[(size_t)kl * 4096 + nl];
        }
        __syncthreads();
        for (int idx = threadIdx.x; idx < 512; idx += 256) {
            int nl = idx >> 4;
            int kp = (idx & 15) * 2;
            int norig = n0 + nl;
            int g = norig >> 10;
            int rem = norig & 1023;
            int np = ((rem >> 5) << 7) + (((rem >> 3) & 3) << 5) + (g << 3) + (rem & 7);
            __half2 hv = __floats2half2_rn(buf[kp][nl], buf[kp + 1][nl]);
            *reinterpret_cast<uint32_t*>(&g_Bpack[(size_t)np * KTOT + k0 + kp]) =
                *reinterpret_cast<uint32_t*>(&hv);
        }
    }
}

// ---------------------------------------------------------------- main GEMM + epilogue
// grid (32 j-blocks, 32 m-blocks), 128 threads = 4 warps (wm 0..1 x wn 0..1),
// warp tile 64 rows x 64 B'cols (4 m16 x 8 n8; nt = 4*jpair + gate).
// 2-stage cp.async pipeline; 3 CTAs/SM.
__global__ void __launch_bounds__(128, 3) lstm_main(const float* __restrict__ c_in,
                                                    const float* __restrict__ bias,
                                                    float* __restrict__ out) {
    extern __shared__ __align__(128) unsigned char smem[];
    const uint32_t sb = smem_u32(smem);
    const int tid  = threadIdx.x;
    const int lane = tid & 31;
    const int warp = tid >> 5;
    const int wm = warp >> 1;       // 0..1 (64 rows)
    const int wn = warp & 1;        // 0..1 (64 B'cols)
    const int bx = blockIdx.x;      // j-block (32 cols)
    const int by = blockIdx.y;      // m-block (128 rows)

    const __half* Ap = g_Apack + (size_t)by * BM * KTOT;
    const __half* Bp = g_Bpack + (size_t)bx * BN * KTOT;

    // 16B chunks per stage: A 128x8=1024, B 1024 -> 16 per thread
    auto load_stage = [&](int it) {
        const uint32_t st = sb + (uint32_t)(it & 1) * STAGE_BYTES;
        const int k0 = it * BK;
#pragma unroll
        for (int i = 0; i < 8; i++) {
            int idx = tid + i * 128;          // 0..1023
            uint32_t r = (uint32_t)(idx >> 3);
            uint32_t c16 = (uint32_t)(idx & 7);
            cpasync16(st + swz(r, c16), Ap + (size_t)r * KTOT + k0 + c16 * 8);
            cpasync16(st + A_STAGE_BYTES + swz(r, c16), Bp + (size_t)r * KTOT + k0 + c16 * 8);
        }
        cp_commit();
    };

    float acc[4][8][4];
#pragma unroll
    for (int i = 0; i < 4; i++)
#pragma unroll
        for (int j = 0; j < 8; j++)
#pragma unroll
            for (int q = 0; q < 4; q++) acc[i][j][q] = 0.0f;

    load_stage(0);

    const int NIT = KTOT / BK;  // 32
    const uint32_t rlo = (uint32_t)(lane & 15);
    const uint32_t csel = (uint32_t)(lane >> 4);

    for (int it = 0; it < NIT; ++it) {
        cp_wait<0>();            // stage it landed (only group in flight)
        __syncthreads();         // + everyone done computing it-1 (other buffer)
        if (it + 1 < NIT) load_stage(it + 1);   // overwrites buffer consumed at it-1

        const uint32_t sA = sb + (uint32_t)(it & 1) * STAGE_BYTES;
        const uint32_t sB = sA + A_STAGE_BYTES;
#pragma unroll
        for (int k16 = 0; k16 < 4; ++k16) {
            uint32_t a[4][4];
#pragma unroll
            for (int mt = 0; mt < 4; ++mt) {
                uint32_t row = (uint32_t)(wm * 64 + mt * 16) + rlo;
                ldsm_x4(a[mt], sA + swz(row, 2 * k16 + csel));
            }
#pragma unroll
            for (int gp = 0; gp < 4; ++gp) {
                uint32_t r4[4];
                uint32_t row = (uint32_t)(wn * 64 + gp * 16) + rlo;
                ldsm_x4(r4, sB + swz(row, 2 * k16 + csel));
#pragma unroll
                for (int mt = 0; mt < 4; ++mt) {
                    mma16816(acc[mt][2 * gp + 0], a[mt], r4[0], r4[2]);
                    mma16816(acc[mt][2 * gp + 1], a[mt], r4[1], r4[3]);
                }
            }
        }
    }

    // ---- epilogue (in-register: nt = 4*jpair + gate)
#pragma unroll
    for (int jp = 0; jp < 2; ++jp) {
        const int jg = bx * 32 + (wn * 2 + jp) * 8 + 2 * (lane & 3);
        float bi[4][2];
#pragma unroll
        for (int g = 0; g < 4; ++g) {
            bi[g][0] = bias[g * 1024 + jg];
            bi[g][1] = bias[g * 1024 + jg + 1];
        }
#pragma unroll
        for (int mt = 0; mt < 4; ++mt) {
#pragma unroll
            for (int hr = 0; hr < 2; ++hr) {
                int m = by * 128 + wm * 64 + mt * 16 + (lane >> 2) + hr * 8;
                const float2 cv = *reinterpret_cast<const float2*>(c_in + (size_t)m * 1024 + jg);
                float hv[2], co[2];
#pragma unroll
                for (int q = 0; q < 2; ++q) {
                    float ai = acc[mt][jp * 4 + 0][hr * 2 + q] + bi[0][q];
                    float af = acc[mt][jp * 4 + 1][hr * 2 + q] + bi[1][q];
                    float ao = acc[mt][jp * 4 + 2][hr * 2 + q] + bi[2][q];
                    float ag = acc[mt][jp * 4 + 3][hr * 2 + q] + bi[3][q];
                    float iv = sigm_f(ai);
                    float fv = sigm_f(af);
                    float ov = sigm_f(ao);
                    float gv = tanh_f(ag);
                    float cc = (q == 0) ? cv.x : cv.y;
                    float c2 = fmaf(iv, gv, fv * cc);
                    co[q] = c2;
                    hv[q] = ov * tanh_f(c2);
                }
                *reinterpret_cast<float2*>(out + (size_t)m * 1024 + jg) = make_float2(hv[0], hv[1]);
                *reinterpret_cast<float2*>(out + (size_t)BATCH * 1024 + (size_t)m * 1024 + jg) =
                    make_float2(co[0], co[1]);
            }
        }
    }
}

// ---------------------------------------------------------------- launch
extern "C" void kernel_launch(void* const* d_in, const int* in_sizes, int n_in,
                              void* d_out, int out_size) {
    (void)in_sizes; (void)n_in; (void)out_size;
    const float* x = (const float*)d_in[0];
    const float* h = (const float*)d_in[1];
    const float* c = (const float*)d_in[2];
    const float* W = (const float*)d_in[3];
    const float* V = (const float*)d_in[4];
    const float* b = (const float*)d_in[5];
    float* out = (float*)d_out;

    cudaFuncSetAttribute(lstm_main, cudaFuncAttributeMaxDynamicSharedMemorySize,
                         STAGES * STAGE_BYTES);

    pack_all<<<16384, 256>>>(x, h, W, V);
    lstm_main<<<dim3(32, 32), 128, STAGES * STAGE_BYTES>>>(c, b, out);
}